// round 3
// baseline (speedup 1.0000x reference)
#include <cuda_runtime.h>

#define B 8
#define N 2048
#define D 128
#define TI 64
#define TJ 64
#define DP 129               // padded row stride (floats) -> conflict-free LDS
#define TEMP (1.0f / 13.544f)

// scratch (allocation-free rule: __device__ globals)
__device__ float g_sq[B * N];
__device__ float g_rowsum[B * N];

// ---------------------------------------------------------------------------
// Kernel 0: per-row squared norms. One warp per row (128 floats = 4/lane).
// ---------------------------------------------------------------------------
__global__ void sq_kernel(const float* __restrict__ x) {
    int row = blockIdx.x * (blockDim.x >> 5) + (threadIdx.x >> 5);
    int lane = threadIdx.x & 31;
    if (row >= B * N) return;
    float4 v = reinterpret_cast<const float4*>(x + (size_t)row * D)[lane];
    float s = v.x * v.x + v.y * v.y + v.z * v.z + v.w * v.w;
    #pragma unroll
    for (int o = 16; o; o >>= 1) s += __shfl_xor_sync(0xffffffffu, s, o);
    if (lane == 0) g_sq[row] = s;
}

// ---------------------------------------------------------------------------
// Kernel 1: per (batch, 64-row tile): sweep all 2048 columns.
//   dot tile 64x64 via 4x4 register tiling (16x16 threads),
//   dist = sq_i - 2*dot + sq_j (clamped), p = exp(-T*dist),
//   write unnormalized p to out, accumulate exact row sums.
// Column/row assignment is strided by 16 so LDS within a warp is
// conflict-free (DP=129 => bank stride 1 across the 16 tx lanes).
// ---------------------------------------------------------------------------
extern __shared__ float smem[];

__global__ void __launch_bounds__(256, 2)
sim_kernel(const float* __restrict__ x, float* __restrict__ out) {
    const int b = blockIdx.y;
    const int i0 = blockIdx.x * TI;

    float* Xi  = smem;                 // TI * DP
    float* Xj  = smem + TI * DP;       // TJ * DP
    float* sqi = Xj + TJ * DP;         // TI
    float* sqj = sqi + TI;             // TJ

    const int tid = threadIdx.x;
    const int tx = tid & 15;
    const int ty = tid >> 4;

    const float* xb = x + (size_t)b * N * D;

    // load Xi tile (coalesced float4 reads, padded smem rows)
    for (int idx = tid; idx < TI * (D / 4); idx += 256) {
        int r  = idx >> 5;        // D/4 == 32
        int k4 = idx & 31;
        float4 v = reinterpret_cast<const float4*>(xb + (size_t)(i0 + r) * D)[k4];
        float* dst = Xi + r * DP + k4 * 4;
        dst[0] = v.x; dst[1] = v.y; dst[2] = v.z; dst[3] = v.w;
    }
    if (tid < TI) sqi[tid] = g_sq[b * N + i0 + tid];

    float rsum[4] = {0.f, 0.f, 0.f, 0.f};

    for (int j0 = 0; j0 < N; j0 += TJ) {
        __syncthreads();   // previous tile's compute done before overwriting Xj
        for (int idx = tid; idx < TJ * (D / 4); idx += 256) {
            int r  = idx >> 5;
            int k4 = idx & 31;
            float4 v = reinterpret_cast<const float4*>(xb + (size_t)(j0 + r) * D)[k4];
            float* dst = Xj + r * DP + k4 * 4;
            dst[0] = v.x; dst[1] = v.y; dst[2] = v.z; dst[3] = v.w;
        }
        if (tid < TJ) sqj[tid] = g_sq[b * N + j0 + tid];
        __syncthreads();

        float acc[4][4];
        #pragma unroll
        for (int ci = 0; ci < 4; ci++)
            #pragma unroll
            for (int cj = 0; cj < 4; cj++) acc[ci][cj] = 0.f;

        #pragma unroll 8
        for (int k = 0; k < D; k++) {
            float a[4], bb[4];
            #pragma unroll
            for (int c = 0; c < 4; c++) a[c]  = Xi[(ty + 16 * c) * DP + k];
            #pragma unroll
            for (int c = 0; c < 4; c++) bb[c] = Xj[(tx + 16 * c) * DP + k];
            #pragma unroll
            for (int ci = 0; ci < 4; ci++)
                #pragma unroll
                for (int cj = 0; cj < 4; cj++)
                    acc[ci][cj] = fmaf(a[ci], bb[cj], acc[ci][cj]);
        }

        // epilogue: dist -> exp -> store + rowsum
        float si[4], sj[4];
        #pragma unroll
        for (int c = 0; c < 4; c++) si[c] = sqi[ty + 16 * c];
        #pragma unroll
        for (int c = 0; c < 4; c++) sj[c] = sqj[tx + 16 * c];

        #pragma unroll
        for (int ci = 0; ci < 4; ci++) {
            int irow = i0 + ty + 16 * ci;
            float* orow = out + ((size_t)(b * N + irow)) * N + j0;
            #pragma unroll
            for (int cj = 0; cj < 4; cj++) {
                float dist = si[ci] - 2.0f * acc[ci][cj] + sj[cj];
                dist = fmaxf(dist, 0.0f);
                float p = __expf(-TEMP * dist);
                rsum[ci] += p;
                orow[tx + 16 * cj] = p;
            }
        }
    }

    // row sums: reduce across the 16 tx lanes (same ty half of the warp)
    #pragma unroll
    for (int ci = 0; ci < 4; ci++) {
        float v = rsum[ci];
        #pragma unroll
        for (int o = 1; o < 16; o <<= 1) v += __shfl_xor_sync(0xffffffffu, v, o);
        if (tx == 0) g_rowsum[b * N + i0 + ty + 16 * ci] = v;
    }
}

// ---------------------------------------------------------------------------
// Kernel 2: normalize out by its row sum (float4 grid-stride).
// ---------------------------------------------------------------------------
__global__ void norm_kernel(float* __restrict__ out) {
    int idx = blockIdx.x * blockDim.x + threadIdx.x;        // one float4 each
    const int total4 = B * N * N / 4;
    if (idx >= total4) return;
    int row = idx >> 9;                                     // N/4 = 512 float4/row
    float inv = __fdividef(1.0f, g_rowsum[row]);
    float4 v = reinterpret_cast<float4*>(out)[idx];
    v.x *= inv; v.y *= inv; v.z *= inv; v.w *= inv;
    reinterpret_cast<float4*>(out)[idx] = v;
}

// ---------------------------------------------------------------------------
extern "C" void kernel_launch(void* const* d_in, const int* in_sizes, int n_in,
                              void* d_out, int out_size) {
    const float* x = (const float*)d_in[0];
    float* out = (float*)d_out;

    // rows' squared norms
    sq_kernel<<<(B * N) / 8, 256>>>(x);

    // main similarity sweep
    size_t smem_bytes = (size_t)(TI * DP + TJ * DP + TI + TJ) * sizeof(float);
    cudaFuncSetAttribute(sim_kernel, cudaFuncAttributeMaxDynamicSharedMemorySize,
                         (int)smem_bytes);
    dim3 grid(N / TI, B);
    sim_kernel<<<grid, 256, smem_bytes>>>(x, out);

    // normalize
    int total4 = B * N * N / 4;
    norm_kernel<<<(total4 + 255) / 256, 256>>>(out);
}

// round 6
// speedup vs baseline: 3.4859x; 3.4859x over previous
#include <cuda_runtime.h>
#include <cuda_bf16.h>
#include <cstdint>

#define B 8
#define N 2048
#define D 128
#define TEMP (1.0f / 13.544f)
#define CLOG (-1.4426950408889634f * TEMP)        /* c = -T*log2(e) < 0 */
#define K2C  (2.0f * 1.4426950408889634f * TEMP)  /* -2c > 0 */

#define PSB 272            /* padded row stride in bytes (136 bf16) */
#define A_BYTES (128 * PSB)

// smem layout (bytes)
#define SM_CSJ0 0
#define SM_CSJ1 512
#define SM_RED  1024
#define SM_A    2048
#define SM_B0   (SM_A + A_BYTES)
#define SM_B1   (SM_B0 + A_BYTES)
#define SM_TOTAL (SM_B1 + A_BYTES)    /* 2048 + 3*34816 = 106496 */

__device__ __nv_bfloat16 g_xbf[B * N * D];
__device__ float g_sq[B * N];

// ---------------- helpers ----------------
__device__ __forceinline__ uint32_t smem_u32(const void* p) {
    uint32_t a;
    asm("{ .reg .u64 t; cvta.to.shared.u64 t, %1; cvt.u32.u64 %0, t; }"
        : "=r"(a) : "l"(p));
    return a;
}
__device__ __forceinline__ void ldsm_x4(uint32_t* r, uint32_t addr) {
    asm volatile("ldmatrix.sync.aligned.m8n8.x4.shared.b16 {%0,%1,%2,%3}, [%4];"
                 : "=r"(r[0]), "=r"(r[1]), "=r"(r[2]), "=r"(r[3]) : "r"(addr));
}
__device__ __forceinline__ void mma_16816(float* d, const uint32_t* a,
                                          const uint32_t* b) {
    asm volatile(
        "mma.sync.aligned.m16n8k16.row.col.f32.bf16.bf16.f32 "
        "{%0,%1,%2,%3}, {%4,%5,%6,%7}, {%8,%9}, {%0,%1,%2,%3};"
        : "+f"(d[0]), "+f"(d[1]), "+f"(d[2]), "+f"(d[3])
        : "r"(a[0]), "r"(a[1]), "r"(a[2]), "r"(a[3]), "r"(b[0]), "r"(b[1]));
}
__device__ __forceinline__ float ex2(float x) {
    float r;
    asm("ex2.approx.ftz.f32 %0, %1;" : "=f"(r) : "f"(x));
    return r;
}
#define CP16(saddr, gptr) \
    asm volatile("cp.async.cg.shared.global [%0], [%1], 16;" \
                 :: "r"(saddr), "l"(gptr))
#define CP_COMMIT() asm volatile("cp.async.commit_group;" ::: "memory")
#define CP_WAIT(n)  asm volatile("cp.async.wait_group %0;" :: "n"(n) : "memory")

// ---------------------------------------------------------------------------
// Prep: fp32 -> bf16 copy; squared norms from the bf16 values (fp32 accum)
// so the MMA diagonal distance cancels to ~0.
// ---------------------------------------------------------------------------
__global__ void prep_kernel(const float* __restrict__ x) {
    int row = blockIdx.x * 8 + (threadIdx.x >> 5);
    int lane = threadIdx.x & 31;
    float4 v = reinterpret_cast<const float4*>(x + (size_t)row * D)[lane];
    __nv_bfloat16 b0 = __float2bfloat16(v.x), b1 = __float2bfloat16(v.y);
    __nv_bfloat16 b2 = __float2bfloat16(v.z), b3 = __float2bfloat16(v.w);
    uint2 pk;
    pk.x = ((uint32_t)__bfloat16_as_ushort(b1) << 16) | __bfloat16_as_ushort(b0);
    pk.y = ((uint32_t)__bfloat16_as_ushort(b3) << 16) | __bfloat16_as_ushort(b2);
    reinterpret_cast<uint2*>(g_xbf + (size_t)row * D)[lane] = pk;
    float a0 = __bfloat162float(b0), a1 = __bfloat162float(b1);
    float a2 = __bfloat162float(b2), a3 = __bfloat162float(b3);
    float s = a0 * a0 + a1 * a1 + a2 * a2 + a3 * a3;
    #pragma unroll
    for (int o = 16; o; o >>= 1) s += __shfl_xor_sync(0xffffffffu, s, o);
    if (lane == 0) g_sq[row] = s;
}

// ---------------------------------------------------------------------------
// Main kernel: CTA = (batch, 128-row band). 8 warps, warp tile 32(i) x 64(j).
// 32 iterations over 16 j-tiles x 2 passes:
//   pass 0: accumulate row sums of exp() in registers
//   pass 1: recompute dots, normalize, store (output written exactly once)
// B tiles double-buffered via cp.async; A fragments persistent in registers.
// ---------------------------------------------------------------------------
__global__ void __launch_bounds__(256, 1)
sim_mma_kernel(float* __restrict__ out) {
    extern __shared__ char smem[];
    const uint32_t sbase = smem_u32(smem);
    const int tid = threadIdx.x;
    const int wid = tid >> 5, lane = tid & 31;
    const int wm = wid & 3;                // 32-row band within 128
    const int wn = wid >> 2;               // 64-col band within 128
    const int b = blockIdx.y;
    const int i0 = blockIdx.x * 128;

    const __nv_bfloat16* xb = g_xbf + (size_t)b * N * D;
    const float* sqb = g_sq + b * N;
    float* csj0 = reinterpret_cast<float*>(smem + SM_CSJ0);
    float* csj1 = reinterpret_cast<float*>(smem + SM_CSJ1);
    float* red  = reinterpret_cast<float*>(smem + SM_RED);

    // ---- prologue: cp.async A tile + B tile 0, csj0 ----
    {
        const int r = tid >> 1, h = tid & 1;
        const char* gA = (const char*)(xb + (size_t)(i0 + r) * D) + h * 128;
        const char* gB = (const char*)(xb + (size_t)r * D) + h * 128;
        uint32_t sA = sbase + SM_A  + r * PSB + h * 128;
        uint32_t sB = sbase + SM_B0 + r * PSB + h * 128;
        #pragma unroll
        for (int q = 0; q < 8; q++) {
            CP16(sA + q * 16, gA + q * 16);
            CP16(sB + q * 16, gB + q * 16);
        }
        CP_COMMIT();
        if (tid < 128) csj0[tid] = CLOG * sqb[tid];
        CP_WAIT(0);
    }
    __syncthreads();

    // ---- persistent A fragments: 2 m-tiles x 8 k-steps x 4 regs ----
    uint32_t afrag[2][8][4];
    {
        uint32_t rowa = sbase + SM_A + (wm * 32 + (lane & 15)) * PSB + (lane >> 4) * 16;
        #pragma unroll
        for (int m = 0; m < 2; m++)
            #pragma unroll
            for (int k = 0; k < 8; k++)
                ldsm_x4(afrag[m][k], rowa + m * 16 * PSB + k * 32);
    }

    // per-thread row constants: rows wm*32 + m*16 + (lane>>2) + s*8
    float csi[2][2], inv[2][2], rsum[2][2];
    #pragma unroll
    for (int m = 0; m < 2; m++)
        #pragma unroll
        for (int s = 0; s < 2; s++) {
            int r = i0 + wm * 32 + m * 16 + (lane >> 2) + s * 8;
            csi[m][s] = CLOG * sqb[r];
            rsum[m][s] = 0.0f;
            inv[m][s] = 0.0f;
        }

    const uint32_t bldbase = sbase + (wn * 64 + (lane & 15)) * PSB + (lane >> 4) * 16;

    for (int tt = 0; tt < 32; tt++) {
        const int buf = tt & 1, nbuf = buf ^ 1;
        __syncthreads();   // compute(tt-1) done reading buf^1 / csj^1

        if (tt < 31) {     // prefetch B(tt+1) into the other buffer
            const int jn = ((tt + 1) & 15) * 128;
            const int r = tid >> 1, h = tid & 1;
            const char* gB = (const char*)(xb + (size_t)(jn + r) * D) + h * 128;
            uint32_t sB = sbase + (nbuf ? SM_B1 : SM_B0) + r * PSB + h * 128;
            #pragma unroll
            for (int q = 0; q < 8; q++) CP16(sB + q * 16, gB + q * 16);
            CP_COMMIT();
            if (tid < 128) (nbuf ? csj1 : csj0)[tid] = CLOG * sqb[jn + tid];
            CP_WAIT(1);
        } else {
            CP_WAIT(0);
        }
        __syncthreads();   // B(tt) + csj(tt) visible

        // ---- MMA: 128x128x128 tile, this warp's 32x64 slice ----
        float acc[2][8][4];
        #pragma unroll
        for (int m = 0; m < 2; m++)
            #pragma unroll
            for (int n = 0; n < 8; n++)
                #pragma unroll
                for (int e = 0; e < 4; e++) acc[m][n][e] = 0.0f;

        const uint32_t bbase = bldbase + (buf ? SM_B1 : SM_B0);
        #pragma unroll
        for (int k = 0; k < 8; k++) {
            uint32_t bfrag[8][2];
            #pragma unroll
            for (int p = 0; p < 4; p++) {
                uint32_t t[4];
                // non-trans: smem row = n (k contiguous) == col-major KxN view,
                // matches mma.row.col B fragment (lane holds 2 consecutive k).
                ldsm_x4(t, bbase + p * 16 * PSB + k * 32);
                bfrag[2 * p][0] = t[0]; bfrag[2 * p][1] = t[2];
                bfrag[2 * p + 1][0] = t[1]; bfrag[2 * p + 1][1] = t[3];
            }
            #pragma unroll
            for (int m = 0; m < 2; m++)
                #pragma unroll
                for (int n = 0; n < 8; n++)
                    mma_16816(acc[m][n], afrag[m][k], bfrag[n]);
        }

        // ---- epilogue ----
        const float* csj = buf ? csj1 : csj0;
        const int j0 = (tt & 15) * 128;
        const int colb = wn * 64 + (lane & 3) * 2;

        if (tt < 16) {
            #pragma unroll
            for (int m = 0; m < 2; m++)
                #pragma unroll
                for (int n = 0; n < 8; n++) {
                    float2 cj = *reinterpret_cast<const float2*>(csj + colb + n * 8);
                    float base0 = csi[m][0], base1 = csi[m][1];
                    float p0 = ex2(fminf(fmaf(K2C, acc[m][n][0], base0 + cj.x), 0.f));
                    float p1 = ex2(fminf(fmaf(K2C, acc[m][n][1], base0 + cj.y), 0.f));
                    float p2 = ex2(fminf(fmaf(K2C, acc[m][n][2], base1 + cj.x), 0.f));
                    float p3 = ex2(fminf(fmaf(K2C, acc[m][n][3], base1 + cj.y), 0.f));
                    rsum[m][0] += p0 + p1;
                    rsum[m][1] += p2 + p3;
                }
        } else {
            #pragma unroll
            for (int m = 0; m < 2; m++) {
                const int r0 = i0 + wm * 32 + m * 16 + (lane >> 2);
                float* orow0 = out + (size_t)(b * N + r0) * N + j0 + colb;
                float* orow1 = orow0 + (size_t)8 * N;
                #pragma unroll
                for (int n = 0; n < 8; n++) {
                    float2 cj = *reinterpret_cast<const float2*>(csj + colb + n * 8);
                    float base0 = csi[m][0], base1 = csi[m][1];
                    float2 w0, w1;
                    w0.x = ex2(fminf(fmaf(K2C, acc[m][n][0], base0 + cj.x), 0.f)) * inv[m][0];
                    w0.y = ex2(fminf(fmaf(K2C, acc[m][n][1], base0 + cj.y), 0.f)) * inv[m][0];
                    w1.x = ex2(fminf(fmaf(K2C, acc[m][n][2], base1 + cj.x), 0.f)) * inv[m][1];
                    w1.y = ex2(fminf(fmaf(K2C, acc[m][n][3], base1 + cj.y), 0.f)) * inv[m][1];
                    *reinterpret_cast<float2*>(orow0 + n * 8) = w0;
                    *reinterpret_cast<float2*>(orow1 + n * 8) = w1;
                }
            }
        }

        // ---- end of pass 0: reduce row sums, compute inverses ----
        if (tt == 15) {
            #pragma unroll
            for (int m = 0; m < 2; m++)
                #pragma unroll
                for (int s = 0; s < 2; s++) {
                    float v = rsum[m][s];
                    v += __shfl_xor_sync(0xffffffffu, v, 1);
                    v += __shfl_xor_sync(0xffffffffu, v, 2);
                    if ((lane & 3) == 0)
                        red[wn * 128 + wm * 32 + m * 16 + (lane >> 2) + s * 8] = v;
                }
            __syncthreads();
            #pragma unroll
            for (int m = 0; m < 2; m++)
                #pragma unroll
                for (int s = 0; s < 2; s++) {
                    int rl = wm * 32 + m * 16 + (lane >> 2) + s * 8;
                    inv[m][s] = __fdividef(1.0f, red[rl] + red[128 + rl]);
                }
        }
    }
}

// ---------------------------------------------------------------------------
extern "C" void kernel_launch(void* const* d_in, const int* in_sizes, int n_in,
                              void* d_out, int out_size) {
    const float* x = (const float*)d_in[0];
    float* out = (float*)d_out;

    prep_kernel<<<(B * N) / 8, 256>>>(x);

    cudaFuncSetAttribute(sim_mma_kernel,
                         cudaFuncAttributeMaxDynamicSharedMemorySize, SM_TOTAL);
    dim3 grid(N / 128, B);
    sim_mma_kernel<<<grid, 256, SM_TOTAL>>>(out);
}

// round 7
// speedup vs baseline: 3.5401x; 1.0156x over previous
#include <cuda_runtime.h>
#include <cuda_bf16.h>
#include <cstdint>

#define B 8
#define N 2048
#define D 128
#define TEMP (1.0f / 13.544f)
#define CLOG (-1.4426950408889634f * TEMP)        /* c = -T*log2(e) < 0 */
#define K2C  (2.0f * 1.4426950408889634f * TEMP)  /* -2c > 0 */

#define PSB 272            /* padded row stride in bytes (136 bf16) */
#define A_BYTES (128 * PSB)

// smem layout (bytes)
#define SM_CSJ0 0
#define SM_CSJ1 512
#define SM_RED  1024                 /* 512 floats = 2048 B */
#define SM_A    3072
#define SM_B0   (SM_A + A_BYTES)
#define SM_B1   (SM_B0 + A_BYTES)
#define SM_TOTAL (SM_B1 + A_BYTES)   /* 3072 + 3*34816 = 107520 */

__device__ __nv_bfloat16 g_xbf[B * N * D];
__device__ float g_sq[B * N];

// ---------------- helpers ----------------
__device__ __forceinline__ uint32_t smem_u32(const void* p) {
    uint32_t a;
    asm("{ .reg .u64 t; cvta.to.shared.u64 t, %1; cvt.u32.u64 %0, t; }"
        : "=r"(a) : "l"(p));
    return a;
}
__device__ __forceinline__ void ldsm_x4(uint32_t* r, uint32_t addr) {
    asm volatile("ldmatrix.sync.aligned.m8n8.x4.shared.b16 {%0,%1,%2,%3}, [%4];"
                 : "=r"(r[0]), "=r"(r[1]), "=r"(r[2]), "=r"(r[3]) : "r"(addr));
}
__device__ __forceinline__ void mma_16816(float* d, const uint32_t* a,
                                          const uint32_t* b) {
    asm volatile(
        "mma.sync.aligned.m16n8k16.row.col.f32.bf16.bf16.f32 "
        "{%0,%1,%2,%3}, {%4,%5,%6,%7}, {%8,%9}, {%0,%1,%2,%3};"
        : "+f"(d[0]), "+f"(d[1]), "+f"(d[2]), "+f"(d[3])
        : "r"(a[0]), "r"(a[1]), "r"(a[2]), "r"(a[3]), "r"(b[0]), "r"(b[1]));
}
__device__ __forceinline__ float ex2(float x) {
    float r;
    asm("ex2.approx.ftz.f32 %0, %1;" : "=f"(r) : "f"(x));
    return r;
}
#define CP16(saddr, gptr) \
    asm volatile("cp.async.cg.shared.global [%0], [%1], 16;" \
                 :: "r"(saddr), "l"(gptr))
#define CP_COMMIT() asm volatile("cp.async.commit_group;" ::: "memory")
#define CP_WAIT(n)  asm volatile("cp.async.wait_group %0;" :: "n"(n) : "memory")

// ---------------------------------------------------------------------------
// Prep: fp32 -> bf16 copy; squared norms from the bf16 values (fp32 accum)
// so the MMA diagonal distance cancels to ~0.
// ---------------------------------------------------------------------------
__global__ void prep_kernel(const float* __restrict__ x) {
    int row = blockIdx.x * 8 + (threadIdx.x >> 5);
    int lane = threadIdx.x & 31;
    float4 v = reinterpret_cast<const float4*>(x + (size_t)row * D)[lane];
    __nv_bfloat16 b0 = __float2bfloat16(v.x), b1 = __float2bfloat16(v.y);
    __nv_bfloat16 b2 = __float2bfloat16(v.z), b3 = __float2bfloat16(v.w);
    uint2 pk;
    pk.x = ((uint32_t)__bfloat16_as_ushort(b1) << 16) | __bfloat16_as_ushort(b0);
    pk.y = ((uint32_t)__bfloat16_as_ushort(b3) << 16) | __bfloat16_as_ushort(b2);
    reinterpret_cast<uint2*>(g_xbf + (size_t)row * D)[lane] = pk;
    float a0 = __bfloat162float(b0), a1 = __bfloat162float(b1);
    float a2 = __bfloat162float(b2), a3 = __bfloat162float(b3);
    float s = a0 * a0 + a1 * a1 + a2 * a2 + a3 * a3;
    #pragma unroll
    for (int o = 16; o; o >>= 1) s += __shfl_xor_sync(0xffffffffu, s, o);
    if (lane == 0) g_sq[row] = s;
}

// ---------------------------------------------------------------------------
// Main kernel: CTA = (batch, 128-row band). 16 warps (4x4), warp tile 32x32.
// 32 iterations over 16 j-tiles x 2 passes:
//   pass 0: accumulate row sums of exp() in registers
//   pass 1: recompute dots, normalize, store (output written exactly once)
// B tiles double-buffered via cp.async; A/B fragments loaded per k-step.
// ---------------------------------------------------------------------------
__global__ void __launch_bounds__(512, 1)
sim_mma_kernel(float* __restrict__ out) {
    extern __shared__ char smem[];
    const uint32_t sbase = smem_u32(smem);
    const int tid = threadIdx.x;
    const int wid = tid >> 5, lane = tid & 31;
    const int wm = wid & 3;                // 32-row band within 128
    const int wn = wid >> 2;               // 32-col band within 128
    const int b = blockIdx.y;
    const int i0 = blockIdx.x * 128;

    const __nv_bfloat16* xb = g_xbf + (size_t)b * N * D;
    const float* sqb = g_sq + b * N;
    float* csj0 = reinterpret_cast<float*>(smem + SM_CSJ0);
    float* csj1 = reinterpret_cast<float*>(smem + SM_CSJ1);
    float* red  = reinterpret_cast<float*>(smem + SM_RED);

    // ---- prologue: cp.async A tile + B tile 0, csj0 ----
    {
        const int r = tid >> 2, c = tid & 3;   // 128 rows x 4 x 64B
        const char* gA = (const char*)(xb + (size_t)(i0 + r) * D) + c * 64;
        const char* gB = (const char*)(xb + (size_t)r * D) + c * 64;
        uint32_t sA = sbase + SM_A  + r * PSB + c * 64;
        uint32_t sB = sbase + SM_B0 + r * PSB + c * 64;
        #pragma unroll
        for (int q = 0; q < 4; q++) {
            CP16(sA + q * 16, gA + q * 16);
            CP16(sB + q * 16, gB + q * 16);
        }
        CP_COMMIT();
        if (tid < 128) csj0[tid] = CLOG * sqb[tid];
        CP_WAIT(0);
    }
    __syncthreads();

    // per-thread row constants: rows wm*32 + m*16 + (lane>>2) + s*8
    float csi[2][2], inv[2][2], rsum[2][2];
    #pragma unroll
    for (int m = 0; m < 2; m++)
        #pragma unroll
        for (int s = 0; s < 2; s++) {
            int r = i0 + wm * 32 + m * 16 + (lane >> 2) + s * 8;
            csi[m][s] = CLOG * sqb[r];
            rsum[m][s] = 0.0f;
            inv[m][s] = 0.0f;
        }

    const uint32_t arow = sbase + SM_A + (wm * 32 + (lane & 15)) * PSB + (lane >> 4) * 16;
    const uint32_t bldbase = sbase + (wn * 32 + (lane & 15)) * PSB + (lane >> 4) * 16;

    for (int tt = 0; tt < 32; tt++) {
        const int buf = tt & 1, nbuf = buf ^ 1;
        __syncthreads();   // compute(tt-1) done reading buf^1 / csj^1

        if (tt < 31) {     // prefetch B(tt+1) into the other buffer
            const int jn = ((tt + 1) & 15) * 128;
            const int r = tid >> 2, c = tid & 3;
            const char* gB = (const char*)(xb + (size_t)(jn + r) * D) + c * 64;
            uint32_t sB = sbase + (nbuf ? SM_B1 : SM_B0) + r * PSB + c * 64;
            #pragma unroll
            for (int q = 0; q < 4; q++) CP16(sB + q * 16, gB + q * 16);
            CP_COMMIT();
            if (tid < 128) (nbuf ? csj1 : csj0)[tid] = CLOG * sqb[jn + tid];
            CP_WAIT(1);
        } else {
            CP_WAIT(0);
        }
        __syncthreads();   // B(tt) + csj(tt) visible

        // ---- MMA: this warp's 32x32 slice of the 128x128 tile ----
        float acc[2][4][4];
        #pragma unroll
        for (int m = 0; m < 2; m++)
            #pragma unroll
            for (int n = 0; n < 4; n++)
                #pragma unroll
                for (int e = 0; e < 4; e++) acc[m][n][e] = 0.0f;

        const uint32_t bbase = bldbase + (buf ? SM_B1 : SM_B0);
        #pragma unroll
        for (int k = 0; k < 8; k++) {
            uint32_t af[2][4];
            ldsm_x4(af[0], arow + k * 32);
            ldsm_x4(af[1], arow + 16 * PSB + k * 32);
            uint32_t bf[4][2];
            {
                uint32_t t[4];
                ldsm_x4(t, bbase + k * 32);
                bf[0][0] = t[0]; bf[0][1] = t[2];
                bf[1][0] = t[1]; bf[1][1] = t[3];
                ldsm_x4(t, bbase + 16 * PSB + k * 32);
                bf[2][0] = t[0]; bf[2][1] = t[2];
                bf[3][0] = t[1]; bf[3][1] = t[3];
            }
            #pragma unroll
            for (int m = 0; m < 2; m++)
                #pragma unroll
                for (int n = 0; n < 4; n++)
                    mma_16816(acc[m][n], af[m], bf[n]);
        }

        // ---- epilogue ----
        const float* csj = buf ? csj1 : csj0;
        const int j0 = (tt & 15) * 128;
        const int colb = wn * 32 + (lane & 3) * 2;

        if (tt < 16) {
            #pragma unroll
            for (int m = 0; m < 2; m++)
                #pragma unroll
                for (int n = 0; n < 4; n++) {
                    float2 cj = *reinterpret_cast<const float2*>(csj + colb + n * 8);
                    float base0 = csi[m][0], base1 = csi[m][1];
                    float p0 = ex2(fminf(fmaf(K2C, acc[m][n][0], base0 + cj.x), 0.f));
                    float p1 = ex2(fminf(fmaf(K2C, acc[m][n][1], base0 + cj.y), 0.f));
                    float p2 = ex2(fminf(fmaf(K2C, acc[m][n][2], base1 + cj.x), 0.f));
                    float p3 = ex2(fminf(fmaf(K2C, acc[m][n][3], base1 + cj.y), 0.f));
                    rsum[m][0] += p0 + p1;
                    rsum[m][1] += p2 + p3;
                }
        } else {
            #pragma unroll
            for (int m = 0; m < 2; m++) {
                const int r0 = i0 + wm * 32 + m * 16 + (lane >> 2);
                float* orow0 = out + (size_t)(b * N + r0) * N + j0 + colb;
                float* orow1 = orow0 + (size_t)8 * N;
                #pragma unroll
                for (int n = 0; n < 4; n++) {
                    float2 cj = *reinterpret_cast<const float2*>(csj + colb + n * 8);
                    float base0 = csi[m][0], base1 = csi[m][1];
                    float2 w0, w1;
                    w0.x = ex2(fminf(fmaf(K2C, acc[m][n][0], base0 + cj.x), 0.f)) * inv[m][0];
                    w0.y = ex2(fminf(fmaf(K2C, acc[m][n][1], base0 + cj.y), 0.f)) * inv[m][0];
                    w1.x = ex2(fminf(fmaf(K2C, acc[m][n][2], base1 + cj.x), 0.f)) * inv[m][1];
                    w1.y = ex2(fminf(fmaf(K2C, acc[m][n][3], base1 + cj.y), 0.f)) * inv[m][1];
                    *reinterpret_cast<float2*>(orow0 + n * 8) = w0;
                    *reinterpret_cast<float2*>(orow1 + n * 8) = w1;
                }
            }
        }

        // ---- end of pass 0: reduce row sums across 4 column bands ----
        if (tt == 15) {
            #pragma unroll
            for (int m = 0; m < 2; m++)
                #pragma unroll
                for (int s = 0; s < 2; s++) {
                    float v = rsum[m][s];
                    v += __shfl_xor_sync(0xffffffffu, v, 1);
                    v += __shfl_xor_sync(0xffffffffu, v, 2);
                    if ((lane & 3) == 0)
                        red[wn * 128 + wm * 32 + m * 16 + (lane >> 2) + s * 8] = v;
                }
            __syncthreads();
            #pragma unroll
            for (int m = 0; m < 2; m++)
                #pragma unroll
                for (int s = 0; s < 2; s++) {
                    int rl = wm * 32 + m * 16 + (lane >> 2) + s * 8;
                    inv[m][s] = __fdividef(1.0f, red[rl] + red[128 + rl] +
                                                 red[256 + rl] + red[384 + rl]);
                }
        }
    }
}

// ---------------------------------------------------------------------------
extern "C" void kernel_launch(void* const* d_in, const int* in_sizes, int n_in,
                              void* d_out, int out_size) {
    const float* x = (const float*)d_in[0];
    float* out = (float*)d_out;

    prep_kernel<<<(B * N) / 8, 256>>>(x);

    cudaFuncSetAttribute(sim_mma_kernel,
                         cudaFuncAttributeMaxDynamicSharedMemorySize, SM_TOTAL);
    dim3 grid(N / 128, B);
    sim_mma_kernel<<<grid, 512, SM_TOTAL>>>(out);
}